// round 5
// baseline (speedup 1.0000x reference)
#include <cuda_runtime.h>
#include <cstdint>

// Problem constants
#define B_ 32
#define T_ 1024
#define D_ 256
#define H_ 256
#define NSPLIT 8   // t-splits for the mean reduction

// Scratch (allocation-free rule: __device__ globals)
__device__ float g_part[B_ * NSPLIT * D_];   // partial t-sums of x
__device__ float g_W[B_ * D_];               // W mlp output
__device__ float g_bv[B_ * D_];              // b mlp output

// ---------------------------------------------------------------------------
// Kernel 1: partial sums over t.  grid (B, NSPLIT), block 256.
// Thread layout: tx in [0,64) indexes a float4 along d; ty in [0,4) strides t.
// ---------------------------------------------------------------------------
__global__ void k_reduce(const float* __restrict__ x)
{
    int b = blockIdx.x;
    int s = blockIdx.y;
    int tx = threadIdx.x & 63;
    int ty = threadIdx.x >> 6;

    const float4* xp = reinterpret_cast<const float4*>(
        x + ((size_t)b * T_ + (size_t)s * (T_ / NSPLIT)) * D_);

    float4 acc = make_float4(0.f, 0.f, 0.f, 0.f);
#pragma unroll 4
    for (int t = ty; t < T_ / NSPLIT; t += 4) {
        float4 v = xp[t * (D_ / 4) + tx];
        acc.x += v.x; acc.y += v.y; acc.z += v.z; acc.w += v.w;
    }

    __shared__ float4 sm[4][64];
    sm[ty][tx] = acc;
    __syncthreads();
    if (ty == 0) {
        float4 a0 = sm[0][tx], a1 = sm[1][tx], a2 = sm[2][tx], a3 = sm[3][tx];
        float4 r;
        r.x = (a0.x + a1.x) + (a2.x + a3.x);
        r.y = (a0.y + a1.y) + (a2.y + a3.y);
        r.z = (a0.z + a1.z) + (a2.z + a3.z);
        r.w = (a0.w + a1.w) + (a2.w + a3.w);
        reinterpret_cast<float4*>(g_part)[(b * NSPLIT + s) * (D_ / 4) + tx] = r;
    }
}

// ---------------------------------------------------------------------------
// Kernel 2: the two MLPs.  grid (B, 2)  [blockIdx.y: 0 -> W path, 1 -> b path]
// block 256 threads; thread j owns hidden unit j (layer 1) and output d=j (layer 2).
// h = gelu_exact(c @ w1^T + b1);  out = h @ w2^T + b2
// w1: [H, D] row-major, w2: [D, H] row-major  -> both dots are over contiguous rows.
// ---------------------------------------------------------------------------
__global__ void k_mlp(const int* __restrict__ len,
                      const float* __restrict__ w1w, const float* __restrict__ w1b,
                      const float* __restrict__ w2w, const float* __restrict__ w2b,
                      const float* __restrict__ v1w, const float* __restrict__ v1b,
                      const float* __restrict__ v2w, const float* __restrict__ v2b)
{
    int b   = blockIdx.x;
    int sel = blockIdx.y;
    const float* W1 = sel ? v1w : w1w;
    const float* B1 = sel ? v1b : w1b;
    const float* W2 = sel ? v2w : w2w;
    const float* B2 = sel ? v2b : w2b;

    __shared__ float c[D_];
    __shared__ float h[H_];

    int j = threadIdx.x;

    // finalize mean
    float s = 0.f;
#pragma unroll
    for (int p = 0; p < NSPLIT; p++)
        s += g_part[(b * NSPLIT + p) * D_ + j];
    c[j] = s / (float)len[b];
    __syncthreads();

    // layer 1
    {
        const float4* row = reinterpret_cast<const float4*>(W1 + (size_t)j * D_);
        const float4* cv  = reinterpret_cast<const float4*>(c);
        float acc = B1[j];
#pragma unroll 8
        for (int i = 0; i < D_ / 4; i++) {
            float4 w = row[i], cc = cv[i];
            acc += w.x * cc.x + w.y * cc.y + w.z * cc.z + w.w * cc.w;
        }
        // exact gelu: 0.5*x*(1+erf(x/sqrt(2)))
        h[j] = 0.5f * acc * (1.f + erff(acc * 0.70710678118654752f));
    }
    __syncthreads();

    // layer 2 (thread j = output dim d)
    {
        const float4* row = reinterpret_cast<const float4*>(W2 + (size_t)j * H_);
        const float4* hv  = reinterpret_cast<const float4*>(h);
        float acc = B2[j];
#pragma unroll 8
        for (int i = 0; i < H_ / 4; i++) {
            float4 w = row[i], hh = hv[i];
            acc += w.x * hh.x + w.y * hh.y + w.z * hh.z + w.w * hh.w;
        }
        (sel ? g_bv : g_W)[b * D_ + j] = acc;
    }
}

// ---------------------------------------------------------------------------
// Kernel 3: elementwise output.
// out[b,t,d] = (t < L[b]) ? (1+W[b,d])*x[b,t,d] + (t==0 ? bvec[b,d] : 0) : 0
// float4 across d.  One thread per float4 -> 2M threads.
// ---------------------------------------------------------------------------
__global__ void k_out(const float* __restrict__ x,
                      const int* __restrict__ len,
                      float* __restrict__ out)
{
    size_t i = (size_t)blockIdx.x * blockDim.x + threadIdx.x;  // float4 index
    // i < B*T*D/4 = 2^21
    int d4  = (int)(i & 63);          // 64 float4 per (b,t) row
    size_t row = i >> 6;              // b*T + t
    int t = (int)(row & (T_ - 1));
    int b = (int)(row >> 10);

    int L = __ldg(&len[b]);
    float4 v;
    if (t < L) {
        float4 xv = reinterpret_cast<const float4*>(x)[i];
        float4 w  = reinterpret_cast<const float4*>(g_W)[b * (D_ / 4) + d4];
        v.x = (1.f + w.x) * xv.x;
        v.y = (1.f + w.y) * xv.y;
        v.z = (1.f + w.z) * xv.z;
        v.w = (1.f + w.w) * xv.w;
        if (t == 0) {
            float4 bb = reinterpret_cast<const float4*>(g_bv)[b * (D_ / 4) + d4];
            v.x += bb.x; v.y += bb.y; v.z += bb.z; v.w += bb.w;
        }
    } else {
        v = make_float4(0.f, 0.f, 0.f, 0.f);
    }
    reinterpret_cast<float4*>(out)[i] = v;
}

// ---------------------------------------------------------------------------
extern "C" void kernel_launch(void* const* d_in, const int* in_sizes, int n_in,
                              void* d_out, int out_size)
{
    const float* x    = (const float*)d_in[0];
    const int*   len  = (const int*)  d_in[1];
    const float* w1w  = (const float*)d_in[2];
    const float* w1b  = (const float*)d_in[3];
    const float* w2w  = (const float*)d_in[4];
    const float* w2b  = (const float*)d_in[5];
    const float* v1w  = (const float*)d_in[6];
    const float* v1b  = (const float*)d_in[7];
    const float* v2w  = (const float*)d_in[8];
    const float* v2b  = (const float*)d_in[9];
    float* out = (float*)d_out;

    dim3 gr(B_, NSPLIT);
    k_reduce<<<gr, 256>>>(x);

    dim3 gm(B_, 2);
    k_mlp<<<gm, 256>>>(len, w1w, w1b, w2w, w2b, v1w, v1b, v2w, v2b);

    const int n4 = B_ * T_ * D_ / 4;          // 2,097,152
    k_out<<<n4 / 256, 256>>>(x, len, out);
}

// round 6
// speedup vs baseline: 1.0210x; 1.0210x over previous
#include <cuda_runtime.h>
#include <cstdint>

// Problem constants
#define B_ 32
#define T_ 1024
#define D_ 256
#define H_ 256
#define NSPLIT 32   // t-splits for the mean reduction (1024 CTAs total)

// Scratch (allocation-free rule: __device__ globals)
__device__ float g_part[B_ * NSPLIT * D_];   // partial t-sums of x (1 MB)
__device__ float g_W[B_ * D_];               // W mlp output
__device__ float g_bv[B_ * D_];              // b mlp output

// ---------------------------------------------------------------------------
// Kernel 1: partial sums over t.  grid (B, NSPLIT) = 1024 blocks, block 256.
// tx in [0,64) indexes float4 along d; ty in [0,4) strides t over 32 rows
// -> 8 fully-unrolled independent loads per thread (MLP=8).
// ---------------------------------------------------------------------------
__global__ void k_reduce(const float* __restrict__ x)
{
    int b = blockIdx.x;
    int s = blockIdx.y;
    int tx = threadIdx.x & 63;
    int ty = threadIdx.x >> 6;

    const int ROWS = T_ / NSPLIT;    // 32
    const float4* xp = reinterpret_cast<const float4*>(
        x + ((size_t)b * T_ + (size_t)s * ROWS) * D_);

    // 8 independent loads, fully unrolled -> front-batched LDG.128
    float4 v[8];
#pragma unroll
    for (int k = 0; k < 8; k++)
        v[k] = xp[(ty + k * 4) * (D_ / 4) + tx];

    float4 acc;
    acc.x = ((v[0].x + v[1].x) + (v[2].x + v[3].x)) + ((v[4].x + v[5].x) + (v[6].x + v[7].x));
    acc.y = ((v[0].y + v[1].y) + (v[2].y + v[3].y)) + ((v[4].y + v[5].y) + (v[6].y + v[7].y));
    acc.z = ((v[0].z + v[1].z) + (v[2].z + v[3].z)) + ((v[4].z + v[5].z) + (v[6].z + v[7].z));
    acc.w = ((v[0].w + v[1].w) + (v[2].w + v[3].w)) + ((v[4].w + v[5].w) + (v[6].w + v[7].w));

    __shared__ float4 sm[4][64];
    sm[ty][tx] = acc;
    __syncthreads();
    if (ty == 0) {
        float4 a0 = sm[0][tx], a1 = sm[1][tx], a2 = sm[2][tx], a3 = sm[3][tx];
        float4 r;
        r.x = (a0.x + a1.x) + (a2.x + a3.x);
        r.y = (a0.y + a1.y) + (a2.y + a3.y);
        r.z = (a0.z + a1.z) + (a2.z + a3.z);
        r.w = (a0.w + a1.w) + (a2.w + a3.w);
        reinterpret_cast<float4*>(g_part)[(b * NSPLIT + s) * (D_ / 4) + tx] = r;
    }
}

// ---------------------------------------------------------------------------
// Kernel 2: the two MLPs.  grid (B, 2)  [blockIdx.y: 0 -> W path, 1 -> b path]
// block 256 threads; thread j owns hidden unit j (layer 1) and output d=j (layer 2).
// ---------------------------------------------------------------------------
__global__ void k_mlp(const int* __restrict__ len,
                      const float* __restrict__ w1w, const float* __restrict__ w1b,
                      const float* __restrict__ w2w, const float* __restrict__ w2b,
                      const float* __restrict__ v1w, const float* __restrict__ v1b,
                      const float* __restrict__ v2w, const float* __restrict__ v2b)
{
    int b   = blockIdx.x;
    int sel = blockIdx.y;
    const float* W1 = sel ? v1w : w1w;
    const float* B1 = sel ? v1b : w1b;
    const float* W2 = sel ? v2w : w2w;
    const float* B2 = sel ? v2b : w2b;

    __shared__ float c[D_];
    __shared__ float h[H_];

    int j = threadIdx.x;

    // finalize mean (g_part is L2-resident: 1 MB just written)
    float s = 0.f;
#pragma unroll
    for (int p = 0; p < NSPLIT; p++)
        s += g_part[(b * NSPLIT + p) * D_ + j];
    c[j] = s / (float)len[b];
    __syncthreads();

    // layer 1
    {
        const float4* row = reinterpret_cast<const float4*>(W1 + (size_t)j * D_);
        const float4* cv  = reinterpret_cast<const float4*>(c);
        float acc = B1[j];
#pragma unroll 8
        for (int i = 0; i < D_ / 4; i++) {
            float4 w = row[i], cc = cv[i];
            acc += w.x * cc.x + w.y * cc.y + w.z * cc.z + w.w * cc.w;
        }
        // exact gelu: 0.5*x*(1+erf(x/sqrt(2)))
        h[j] = 0.5f * acc * (1.f + erff(acc * 0.70710678118654752f));
    }
    __syncthreads();

    // layer 2 (thread j = output dim d)
    {
        const float4* row = reinterpret_cast<const float4*>(W2 + (size_t)j * H_);
        const float4* hv  = reinterpret_cast<const float4*>(h);
        float acc = B2[j];
#pragma unroll 8
        for (int i = 0; i < H_ / 4; i++) {
            float4 w = row[i], hh = hv[i];
            acc += w.x * hh.x + w.y * hh.y + w.z * hh.z + w.w * hh.w;
        }
        (sel ? g_bv : g_W)[b * D_ + j] = acc;
    }
}

// ---------------------------------------------------------------------------
// Kernel 3: elementwise output, warp-per-row.
// out[b,t,d] = (t < L[b]) ? (1+W[b,d])*x[b,t,d] + (t==0 ? bvec[b,d] : 0) : 0
// One warp owns a (b,t) row: 64 float4 / 32 lanes = 2 float4 per lane.
// Branch on t<L is warp-uniform. Block 256 = 8 rows; grid B*T/8 = 4096.
// ---------------------------------------------------------------------------
__global__ void k_out(const float* __restrict__ x,
                      const int* __restrict__ len,
                      float* __restrict__ out)
{
    int w    = threadIdx.x >> 5;
    int lane = threadIdx.x & 31;
    int row  = blockIdx.x * 8 + w;        // b*T + t
    int t = row & (T_ - 1);
    int b = row >> 10;

    size_t i0 = (size_t)row * 64 + lane;  // float4 index, lane and lane+32
    float4* o4 = reinterpret_cast<float4*>(out);

    int L = __ldg(&len[b]);
    if (t < L) {
        const float4* x4 = reinterpret_cast<const float4*>(x);
        float4 xa = x4[i0];
        float4 xb = x4[i0 + 32];
        float4 wa = reinterpret_cast<const float4*>(g_W)[b * 64 + lane];
        float4 wb = reinterpret_cast<const float4*>(g_W)[b * 64 + lane + 32];
        float4 va, vb;
        va.x = (1.f + wa.x) * xa.x;  va.y = (1.f + wa.y) * xa.y;
        va.z = (1.f + wa.z) * xa.z;  va.w = (1.f + wa.w) * xa.w;
        vb.x = (1.f + wb.x) * xb.x;  vb.y = (1.f + wb.y) * xb.y;
        vb.z = (1.f + wb.z) * xb.z;  vb.w = (1.f + wb.w) * xb.w;
        if (t == 0) {
            float4 ba = reinterpret_cast<const float4*>(g_bv)[b * 64 + lane];
            float4 bb = reinterpret_cast<const float4*>(g_bv)[b * 64 + lane + 32];
            va.x += ba.x; va.y += ba.y; va.z += ba.z; va.w += ba.w;
            vb.x += bb.x; vb.y += bb.y; vb.z += bb.z; vb.w += bb.w;
        }
        o4[i0]      = va;
        o4[i0 + 32] = vb;
    } else {
        float4 z = make_float4(0.f, 0.f, 0.f, 0.f);
        o4[i0]      = z;
        o4[i0 + 32] = z;
    }
}

// ---------------------------------------------------------------------------
extern "C" void kernel_launch(void* const* d_in, const int* in_sizes, int n_in,
                              void* d_out, int out_size)
{
    const float* x    = (const float*)d_in[0];
    const int*   len  = (const int*)  d_in[1];
    const float* w1w  = (const float*)d_in[2];
    const float* w1b  = (const float*)d_in[3];
    const float* w2w  = (const float*)d_in[4];
    const float* w2b  = (const float*)d_in[5];
    const float* v1w  = (const float*)d_in[6];
    const float* v1b  = (const float*)d_in[7];
    const float* v2w  = (const float*)d_in[8];
    const float* v2b  = (const float*)d_in[9];
    float* out = (float*)d_out;

    dim3 gr(B_, NSPLIT);
    k_reduce<<<gr, 256>>>(x);

    dim3 gm(B_, 2);
    k_mlp<<<gm, 256>>>(len, w1w, w1b, w2w, w2b, v1w, v1b, v2w, v2b);

    k_out<<<B_ * T_ / 8, 256>>>(x, len, out);
}